// round 16
// baseline (speedup 1.0000x reference)
#include <cuda_runtime.h>
#include <cuda_bf16.h>
#include <math.h>
#include <stdint.h>

#define B_ 2048
#define D_ 512
#define C_ 10000
#define CPAD 10112          // 79 * 128
#define NTC 79              // AAM col tiles of 128
#define NQCT 32             // QK col tiles of 64
#define NMT 8               // row tiles of 256
#define NAAMBLK (NTC * NMT)           // 632
#define NQKBLK  (NQCT * NMT)          // 256
#define NMEGA (NAAMBLK + NQKBLK)      // 888
#define NFINAL 8

// ---------- scratch (device globals: alloc-free, capture-safe) ----------
__device__ __nv_bfloat16 g_xh[B_ * D_];
__device__ __nv_bfloat16 g_wh[(size_t)CPAD * D_];
__device__ __nv_bfloat16 g_wmh[B_ * D_];
__device__ __nv_bfloat16 g_wkh[B_ * D_];
__device__ float g_rexp[B_];
__device__ float g_rsum[B_];
__device__ float g_nmp[B_];
__device__ float g_cy[B_];
__device__ float g_expneg[B_];
__device__ float g_cos_apm[B_];
__device__ float g_sin_apm[B_];
__device__ float g_acc[3];
__device__ unsigned g_ticket;

// ---------- constants ----------
constexpr float K_S    = 30.0f;
constexpr float K_COSM = 0.9800665778412416f;
constexpr float K_SINM = 0.19866933079506122f;
constexpr float K_TH   = -0.9800665778412416f;
constexpr float K_MM   = 0.039733866159012244f;
constexpr float K_EPS  = 0.1f;
constexpr float K_L2E  = 1.4426950408889634f;
constexpr float K_LN2  = 0.6931471805599453f;

// ---------- fast math (MUFU) ----------
__device__ __forceinline__ float exp_approx(float x) {
    float r;
    asm("ex2.approx.f32 %0, %1;" : "=f"(r) : "f"(x * K_L2E));
    return r;
}
__device__ __forceinline__ float log_approx(float x) {
    float r;
    asm("lg2.approx.f32 %0, %1;" : "=f"(r) : "f"(x));
    return r * K_LN2;
}
__device__ __forceinline__ float sqrt_approx(float x) {
    float r;
    asm("sqrt.approx.f32 %0, %1;" : "=f"(r) : "f"(x));
    return r;
}

// ---------- block-wide sum (final_combine only) ----------
__device__ __forceinline__ float block_sum_all(float v) {
    __shared__ float sh[33];
    int lane = threadIdx.x & 31, wid = threadIdx.x >> 5;
#pragma unroll
    for (int o = 16; o; o >>= 1) v += __shfl_down_sync(0xffffffffu, v, o);
    __syncthreads();
    if (lane == 0) sh[wid] = v;
    __syncthreads();
    if (threadIdx.x == 0) {
        float s = 0.f;
        int nw = (blockDim.x + 31) >> 5;
        for (int w = 0; w < nw; w++) s += sh[w];
        sh[32] = s;
    }
    __syncthreads();
    return sh[32];
}

// ---------- warp-per-row normalize helpers ----------
__device__ __forceinline__ void write_norm_bf16(const float4* v, float inv,
                                                __nv_bfloat16* dst, int lane) {
    uint32_t po[8];
#pragma unroll
    for (int e = 0; e < 4; e++) {
        __nv_bfloat162 p0 = __floats2bfloat162_rn(v[e].x * inv, v[e].y * inv);
        __nv_bfloat162 p1 = __floats2bfloat162_rn(v[e].z * inv, v[e].w * inv);
        po[2 * e + 0] = *(uint32_t*)&p0;
        po[2 * e + 1] = *(uint32_t*)&p1;
    }
    uint4* dp = (uint4*)(dst + lane * 16);
    dp[0] = make_uint4(po[0], po[1], po[2], po[3]);
    dp[1] = make_uint4(po[4], po[5], po[6], po[7]);
}

__device__ __forceinline__ void warp_norm(const float* __restrict__ src,
                                          __nv_bfloat16* __restrict__ dst, int lane) {
    const float4* sp = (const float4*)src + lane * 4;
    float4 v[4];
    float ss = 0.f;
#pragma unroll
    for (int e = 0; e < 4; e++) {
        v[e] = sp[e];
        ss += v[e].x * v[e].x + v[e].y * v[e].y + v[e].z * v[e].z + v[e].w * v[e].w;
    }
#pragma unroll
    for (int o = 16; o; o >>= 1) ss += __shfl_xor_sync(0xffffffffu, ss, o);
    write_norm_bf16(v, 1.0f / fmaxf(sqrtf(ss), 1e-12f), dst, lane);
}

__device__ __forceinline__ void warp_norm2(const float* __restrict__ s0,
                                           const float* __restrict__ s1,
                                           __nv_bfloat16* __restrict__ d0,
                                           __nv_bfloat16* __restrict__ d1, int lane) {
    const float4* p0 = (const float4*)s0 + lane * 4;
    const float4* p1 = (const float4*)s1 + lane * 4;
    float4 v0[4], v1[4];
#pragma unroll
    for (int e = 0; e < 4; e++) v0[e] = p0[e];
#pragma unroll
    for (int e = 0; e < 4; e++) v1[e] = p1[e];
    float ss0 = 0.f, ss1 = 0.f;
#pragma unroll
    for (int e = 0; e < 4; e++) {
        ss0 += v0[e].x * v0[e].x + v0[e].y * v0[e].y + v0[e].z * v0[e].z + v0[e].w * v0[e].w;
        ss1 += v1[e].x * v1[e].x + v1[e].y * v1[e].y + v1[e].z * v1[e].z + v1[e].w * v1[e].w;
    }
#pragma unroll
    for (int o = 16; o; o >>= 1) {
        ss0 += __shfl_xor_sync(0xffffffffu, ss0, o);
        ss1 += __shfl_xor_sync(0xffffffffu, ss1, o);
    }
    write_norm_bf16(v0, 1.0f / fmaxf(sqrtf(ss0), 1e-12f), d0, lane);
    write_norm_bf16(v1, 1.0f / fmaxf(sqrtf(ss1), 1e-12f), d1, lane);
}

#define NB_W (CPAD / 16)            // 632
#define NB_X (B_ / 16)              // 128
#define NB_G (B_ / 8)               // 256
#define NB_ZERO 8
#define PREP_XB NB_W
#define PREP_GB (NB_W + NB_X)
#define PREP_ZB (NB_W + NB_X + NB_G)
#define PREP_GRID (PREP_ZB + NB_ZERO)

__global__ void __launch_bounds__(256)
prep_kernel(const float* __restrict__ x, const float* __restrict__ w,
            const float* __restrict__ wm, const float* __restrict__ wk,
            const int* __restrict__ label) {
    int b = blockIdx.x, t = threadIdx.x;
    int wv = t >> 5, lane = t & 31;
    if (b < PREP_XB) {
        int r0 = b * 16 + wv * 2;
        if (r0 + 1 < C_) {
            warp_norm2(w + (size_t)r0 * D_, w + (size_t)(r0 + 1) * D_,
                       g_wh + (size_t)r0 * D_, g_wh + (size_t)(r0 + 1) * D_, lane);
        } else {
#pragma unroll
            for (int rr = 0; rr < 2; rr++) {
                int row = r0 + rr;
                __nv_bfloat16* dst = g_wh + (size_t)row * D_;
                if (row >= C_) {
                    uint4* dp = (uint4*)(dst + lane * 16);
                    uint4 z = make_uint4(0u, 0u, 0u, 0u);
                    dp[0] = z; dp[1] = z;
                } else {
                    warp_norm(w + (size_t)row * D_, dst, lane);
                }
            }
        }
    } else if (b < PREP_GB) {
        int r0 = (b - PREP_XB) * 16 + wv * 2;
        warp_norm2(x + (size_t)r0 * D_, x + (size_t)(r0 + 1) * D_,
                   g_xh + (size_t)r0 * D_, g_xh + (size_t)(r0 + 1) * D_, lane);
    } else if (b < PREP_ZB) {
        int i = (b - PREP_GB) * 8 + wv;
        int c = label[i];
        const float4* xp = (const float4*)(x  + (size_t)i * D_) + lane * 4;
        const float4* qp = (const float4*)(wm + (size_t)c * D_) + lane * 4;
        const float4* kp = (const float4*)(wk + (size_t)c * D_) + lane * 4;
        float4 qv[4], kv[4];
        float xx = 0.f, xq = 0.f, qq = 0.f, xk = 0.f, kk = 0.f;
#pragma unroll
        for (int e = 0; e < 4; e++) {
            float4 xv = xp[e];
            qv[e] = qp[e];
            kv[e] = kp[e];
            xx += xv.x * xv.x + xv.y * xv.y + xv.z * xv.z + xv.w * xv.w;
            xq += xv.x * qv[e].x + xv.y * qv[e].y + xv.z * qv[e].z + xv.w * qv[e].w;
            qq += qv[e].x * qv[e].x + qv[e].y * qv[e].y + qv[e].z * qv[e].z + qv[e].w * qv[e].w;
            xk += xv.x * kv[e].x + xv.y * kv[e].y + xv.z * kv[e].z + xv.w * kv[e].w;
            kk += kv[e].x * kv[e].x + kv[e].y * kv[e].y + kv[e].z * kv[e].z + kv[e].w * kv[e].w;
        }
#pragma unroll
        for (int o = 16; o; o >>= 1) {
            xx += __shfl_xor_sync(0xffffffffu, xx, o);
            xq += __shfl_xor_sync(0xffffffffu, xq, o);
            qq += __shfl_xor_sync(0xffffffffu, qq, o);
            xk += __shfl_xor_sync(0xffffffffu, xk, o);
            kk += __shfl_xor_sync(0xffffffffu, kk, o);
        }
        write_norm_bf16(qv, 1.0f / fmaxf(sqrtf(qq), 1e-12f), g_wmh + (size_t)i * D_, lane);
        write_norm_bf16(kv, 1.0f / fmaxf(sqrtf(kk), 1e-12f), g_wkh + (size_t)i * D_, lane);
        if (lane == 0) {
            float dq = xq / fmaxf(sqrtf(xx * qq), 1e-24f);
            float dk = xk / fmaxf(sqrtf(xx * kk), 1e-24f);
            float ap = dq * dk;                 // == ap_m exactly
            float ca = fminf(fmaxf(ap, 0.f), 1.f);
            float sa = sqrt_approx(fminf(fmaxf(1.f - ca, 0.f), 1.f));
            g_cos_apm[i] = ca;
            g_sin_apm[i] = sa;
            float pc = ca * ca - sa * sa;
            float ps = sqrt_approx(fminf(fmaxf(1.f - pc, 0.f), 1.f));
            float phi_pm = pc * K_COSM - ps * K_SINM;
            g_expneg[i] = exp_approx(1.f - phi_pm);
        }
    } else {
        int idx = (b - PREP_ZB) * 256 + t;
        g_rexp[idx] = 0.f;
        g_rsum[idx] = 0.f;
        g_nmp[idx]  = 0.f;
        if (b == PREP_ZB) {
            if (t < 3) g_acc[t] = 0.f;
            if (t == 3) g_ticket = 0u;
        }
    }
}

// ============== mma.sync bf16 building blocks ==============
__device__ __forceinline__ void ldsm4(uint32_t& r0, uint32_t& r1, uint32_t& r2, uint32_t& r3,
                                      uint32_t addr) {
    asm volatile("ldmatrix.sync.aligned.m8n8.x4.shared.b16 {%0,%1,%2,%3},[%4];\n"
                 : "=r"(r0), "=r"(r1), "=r"(r2), "=r"(r3) : "r"(addr));
}
__device__ __forceinline__ void mma16816(float* c, const uint32_t* a, uint32_t b0, uint32_t b1) {
    asm volatile("mma.sync.aligned.m16n8k16.row.col.f32.bf16.bf16.f32 "
                 "{%0,%1,%2,%3},{%4,%5,%6,%7},{%8,%9},{%0,%1,%2,%3};\n"
                 : "+f"(c[0]), "+f"(c[1]), "+f"(c[2]), "+f"(c[3])
                 : "r"(a[0]), "r"(a[1]), "r"(a[2]), "r"(a[3]), "r"(b0), "r"(b1));
}
__device__ __forceinline__ void cpasync16(uint32_t s, const void* g) {
    asm volatile("cp.async.cg.shared.global [%0],[%1],16;\n" :: "r"(s), "l"(g));
}

#define ROWB 80
#define A_B (256 * ROWB)            // A region: 256 rows = 20480 B
#define STAGEB (384 * ROWB)         // A:256 + B:128 rows = 30720 B (same for QK)
#define NSTAGE 4
#define GEMM_SMEM (NSTAGE * STAGEB) // 122880 B
#define NIT_ 16
#define WAITS(it) do {                                                     \
    if ((it) <= NIT_ - 3)      asm volatile("cp.async.wait_group 2;\n");   \
    else if ((it) == NIT_ - 2) asm volatile("cp.async.wait_group 1;\n");   \
    else                       asm volatile("cp.async.wait_group 0;\n");   \
} while (0)

// ---------------- AAM role (256x128 tile, 4m x 2n warps, warp tile 64x64) ----------------
struct TileCtx {
    uint32_t aOff[4], bOff[4];
    uint32_t sa, sb;
    const __nv_bfloat16 *pa, *pb;
    int wm, wn, lane;
};

__device__ __forceinline__ void tile_init(TileCtx& T, uint32_t sbase, int tid,
                                          const __nv_bfloat16* A, const __nv_bfloat16* Bm,
                                          int bm, int bn) {
    int lane = tid & 31, warp = tid >> 5;
    T.lane = lane;
    T.wm = warp >> 1; T.wn = warp & 1;
    uint32_t sA0 = sbase, sB0 = sbase + A_B;
    int aRow = T.wm * 64 + (lane & 7) + ((lane >> 3) & 1) * 8;
    int aCol = ((lane >> 4) & 1) * 16;
    int bRow = T.wn * 64 + (lane & 7) + ((lane >> 4) & 1) * 8;
    int bCol = ((lane >> 3) & 1) * 16;
#pragma unroll
    for (int mi = 0; mi < 4; mi++) T.aOff[mi] = sA0 + (uint32_t)((aRow + mi * 16) * ROWB + aCol);
#pragma unroll
    for (int nn = 0; nn < 4; nn++) T.bOff[nn] = sB0 + (uint32_t)((bRow + nn * 16) * ROWB + bCol);
    // loaders: chunk idx = tid + i*256; row = (tid>>2)+i*64, col = tid&3
    int lr = tid >> 2, lc = tid & 3;
    T.sa = sA0 + lr * ROWB + lc * 16;
    T.sb = sB0 + lr * ROWB + lc * 16;
    T.pa = A + (size_t)(bm + lr) * D_ + lc * 8;
    T.pb = Bm + (size_t)(bn + lr) * D_ + lc * 8;
}

__device__ __forceinline__ void tile_load(const TileCtx& T, int stage, int k0) {
    uint32_t so = (uint32_t)(stage * STAGEB);
#pragma unroll
    for (int i = 0; i < 4; i++)      // A: 256 rows
        cpasync16(T.sa + so + i * (64 * ROWB), T.pa + k0 + (size_t)i * 64 * D_);
#pragma unroll
    for (int i = 0; i < 2; i++)      // B: 128 rows
        cpasync16(T.sb + so + i * (64 * ROWB), T.pb + k0 + (size_t)i * 64 * D_);
    asm volatile("cp.async.commit_group;\n");
}

__device__ __forceinline__ void tile_compute(const TileCtx& T, int stage, float acc[4][8][4]) {
    uint32_t soff = (uint32_t)(stage * STAGEB);
#pragma unroll
    for (int ks = 0; ks < 2; ks++) {
        uint32_t a[4][4];
#pragma unroll
        for (int mi = 0; mi < 4; mi++)
            ldsm4(a[mi][0], a[mi][1], a[mi][2], a[mi][3], T.aOff[mi] + soff + ks * 32);
        uint32_t b[8][2];
#pragma unroll
        for (int nn = 0; nn < 4; nn++) {
            uint32_t r0, r1, r2, r3;
            ldsm4(r0, r1, r2, r3, T.bOff[nn] + soff + ks * 32);
            b[2 * nn][0] = r0; b[2 * nn][1] = r1;
            b[2 * nn + 1][0] = r2; b[2 * nn + 1][1] = r3;
        }
#pragma unroll
        for (int mi = 0; mi < 4; mi++)
#pragma unroll
            for (int ni = 0; ni < 8; ni++)
                mma16816(acc[mi][ni], a[mi], b[ni][0], b[ni][1]);
    }
}

// ---------------- QK role (256x64 tile, dual accumulators, warp tile 64x32) ----------------
struct QkCtx {
    uint32_t aOff[4], bqOff[2], bkOff[2];
    uint32_t sa, sq, sk;
    const __nv_bfloat16 *pa, *pq, *pk;
    int wm, wn, lane;
};

__device__ __forceinline__ void qk_init(QkCtx& T, uint32_t sbase, int tid,
                                        const __nv_bfloat16* A, const __nv_bfloat16* Bq,
                                        const __nv_bfloat16* Bk, int bm, int bn) {
    int lane = tid & 31, warp = tid >> 5;
    T.lane = lane;
    T.wm = warp >> 1; T.wn = warp & 1;
    uint32_t sA0 = sbase, sQ0 = sbase + A_B, sK0 = sQ0 + 64 * ROWB;
    int aRow = T.wm * 64 + (lane & 7) + ((lane >> 3) & 1) * 8;
    int aCol = ((lane >> 4) & 1) * 16;
    int bRow = T.wn * 32 + (lane & 7) + ((lane >> 4) & 1) * 8;
    int bCol = ((lane >> 3) & 1) * 16;
#pragma unroll
    for (int mi = 0; mi < 4; mi++) T.aOff[mi] = sA0 + (uint32_t)((aRow + mi * 16) * ROWB + aCol);
#pragma unroll
    for (int nn = 0; nn < 2; nn++) {
        T.bqOff[nn] = sQ0 + (uint32_t)((bRow + nn * 16) * ROWB + bCol);
        T.bkOff[nn] = sK0 + (uint32_t)((bRow + nn * 16) * ROWB + bCol);
    }
    int lr = tid >> 2, lc = tid & 3;
    T.sa = sA0 + lr * ROWB + lc * 16;
    T.pa = A + (size_t)(bm + lr) * D_ + lc * 8;
    T.sq = sQ0 + lr * ROWB + lc * 16;     // lr < 64 handled by guard-free: 256 threads
    T.sk = sK0 + lr * ROWB + lc * 16;
    T.pq = Bq + (size_t)(bn + lr) * D_ + lc * 8;
    T.pk = Bk + (size_t)(bn + lr) * D_ + lc * 8;
}

__device__ __forceinline__ void qk_load(const QkCtx& T, int stage, int k0, int tid) {
    uint32_t so = (uint32_t)(stage * STAGEB);
#pragma unroll
    for (int i = 0; i < 4; i++)      // A: 256 rows
        cpasync16(T.sa + so + i * (64 * ROWB), T.pa + k0 + (size_t)i * 64 * D_);
    if (tid < 256) {                 // q/k: 64 rows each -> threads 0..255 cover via lr<64 check
        if ((tid >> 2) < 64) {
            cpasync16(T.sq + so, T.pq + k0);
            cpasync16(T.sk + so, T.pk + k0);
        }
    }
    asm volatile("cp.async.commit_group;\n");
}

__device__ __forceinline__ void qk_compute(const QkCtx& T, int stage,
                                           float aq[4][4][4], float ak[4][4][4]) {
    uint32_t soff = (uint32_t)(stage * STAGEB);
#pragma unroll
    for (int ks = 0; ks < 2; ks++) {
        uint32_t a[4][4];
#pragma unroll
        for (int mi = 0; mi < 4; mi++)
            ldsm4(a[mi][0], a[mi][1], a[mi][2], a[mi][3], T.aOff[mi] + soff + ks * 32);
        uint32_t bq[4][2], bk[4][2];
#pragma unroll
        for (int nn = 0; nn < 2; nn++) {
            uint32_t r0, r1, r2, r3;
            ldsm4(r0, r1, r2, r3, T.bqOff[nn] + soff + ks * 32);
            bq[2 * nn][0] = r0; bq[2 * nn][1] = r1;
            bq[2 * nn + 1][0] = r2; bq[2 * nn + 1][1] = r3;
            ldsm4(r0, r1, r2, r3, T.bkOff[nn] + soff + ks * 32);
            bk[2 * nn][0] = r0; bk[2 * nn][1] = r1;
            bk[2 * nn + 1][0] = r2; bk[2 * nn + 1][1] = r3;
        }
#pragma unroll
        for (int mi = 0; mi < 4; mi++)
#pragma unroll
            for (int ni = 0; ni < 4; ni++) {
                mma16816(aq[mi][ni], a[mi], bq[ni][0], bq[ni][1]);
                mma16816(ak[mi][ni], a[mi], bk[ni][0], bk[ni][1]);
            }
    }
}

// ---------- nm term ----------
__device__ __forceinline__ float nm_term(float sim, float capm, float sapm) {
    float ca = fminf(fmaxf(sim, 0.f), 1.f);
    float sa = sqrt_approx(fminf(fmaxf(1.f - ca, 0.f), 1.f));
    float ss = sa * capm + ca * sapm;
    float cc = sqrt_approx(fminf(fmaxf(1.f - ss, 0.f), 1.f));
    return exp_approx(ss * K_COSM - cc * K_SINM);
}

// ============== mega kernel: big-tile roles, 1 CTA/SM ==============
__global__ void __launch_bounds__(256, 1)
mega_gemm(const __nv_bfloat16* __restrict__ Axh, const __nv_bfloat16* __restrict__ Bw,
          const __nv_bfloat16* __restrict__ Bwm, const __nv_bfloat16* __restrict__ Bwk,
          const int* __restrict__ label) {
    extern __shared__ __align__(16) char smem[];
    uint32_t sbase = (uint32_t)__cvta_generic_to_shared(smem);
    int tid = threadIdx.x;

    if (blockIdx.x < NAAMBLK) {
        int bx = blockIdx.x % NTC, by = blockIdx.x / NTC;
        int bm = by * 256, bn = bx * 128;
        TileCtx T;
        tile_init(T, sbase, tid, Axh, Bw, bm, bn);
        float acc[4][8][4];
#pragma unroll
        for (int mi = 0; mi < 4; mi++)
#pragma unroll
            for (int ni = 0; ni < 8; ni++)
#pragma unroll
                for (int e = 0; e < 4; e++) acc[mi][ni][e] = 0.f;

        tile_load(T, 0, 0);
        tile_load(T, 1, 32);
        tile_load(T, 2, 64);
#pragma unroll
        for (int it = 0; it < NIT_; it++) {
            WAITS(it);
            __syncthreads();
            tile_compute(T, it & 3, acc);
            if (it + 3 < NIT_) tile_load(T, (it + 3) & 3, (it + 3) * 32);
        }

        int lane = T.lane;
        int colbase = bn + T.wn * 64 + (lane & 3) * 2;
#pragma unroll
        for (int mi = 0; mi < 4; mi++) {
#pragma unroll
            for (int h = 0; h < 2; h++) {
                int row = bm + T.wm * 64 + mi * 16 + (lane >> 2) + h * 8;
                int lab = label[row];
                float se = 0.f, sc = 0.f, cy = 0.f;
#pragma unroll
                for (int ni = 0; ni < 8; ni++) {
                    int col = colbase + ni * 8;
                    float v0 = acc[mi][ni][h * 2 + 0];
                    float v1 = acc[mi][ni][h * 2 + 1];
                    if (col < C_) {
                        sc += v0;
                        se += exp_approx(K_S * (v0 - 1.f));
                        if (col == lab) cy = v0;
                    }
                    if (col + 1 < C_) {
                        sc += v1;
                        se += exp_approx(K_S * (v1 - 1.f));
                        if (col + 1 == lab) cy = v1;
                    }
                }
                se += __shfl_xor_sync(0xffffffffu, se, 1);
                se += __shfl_xor_sync(0xffffffffu, se, 2);
                sc += __shfl_xor_sync(0xffffffffu, sc, 1);
                sc += __shfl_xor_sync(0xffffffffu, sc, 2);
                cy += __shfl_xor_sync(0xffffffffu, cy, 1);
                cy += __shfl_xor_sync(0xffffffffu, cy, 2);
                if ((lane & 3) == 0) {
                    atomicAdd(&g_rexp[row], se);
                    atomicAdd(&g_rsum[row], sc);
                    int cb = bn + T.wn * 64;
                    if (lab >= cb && lab < cb + 64) g_cy[row] = cy;
                }
            }
        }
    } else {
        int idx = blockIdx.x - NAAMBLK;
        int cn = idx % NQCT, rm = idx / NQCT;
        int bm = rm * 256, bn = cn * 64;
        QkCtx T;
        qk_init(T, sbase, tid, Axh, Bwm, Bwk, bm, bn);
        float aq[4][4][4], ak[4][4][4];
#pragma unroll
        for (int mi = 0; mi < 4; mi++)
#pragma unroll
            for (int ni = 0; ni < 4; ni++)
#pragma unroll
                for (int e = 0; e < 4; e++) { aq[mi][ni][e] = 0.f; ak[mi][ni][e] = 0.f; }

        qk_load(T, 0, 0, tid);
        qk_load(T, 1, 32, tid);
        qk_load(T, 2, 64, tid);
#pragma unroll
        for (int it = 0; it < NIT_; it++) {
            WAITS(it);
            __syncthreads();
            qk_compute(T, it & 3, aq, ak);
            if (it + 3 < NIT_) qk_load(T, (it + 3) & 3, (it + 3) * 32, tid);
        }

        __syncthreads();
        float* s_capm = (float*)smem;            // [64]
        float* s_sapm = s_capm + 64;             // [64]
        int*   s_lcol = (int*)(s_sapm + 64);     // [64]
        int*   s_lrow = s_lcol + 64;             // [256]
        if (tid < 64) {
            s_capm[tid] = g_cos_apm[bn + tid];
            s_sapm[tid] = g_sin_apm[bn + tid];
            s_lcol[tid] = label[bn + tid];
        }
        s_lrow[tid] = label[bm + tid];
        __syncthreads();

        int lane = T.lane;
        int colloc0 = T.wn * 32 + (lane & 3) * 2;
#pragma unroll
        for (int mi = 0; mi < 4; mi++) {
#pragma unroll
            for (int h = 0; h < 2; h++) {
                int rloc = T.wm * 64 + mi * 16 + (lane >> 2) + h * 8;
                int row = bm + rloc;
                int lrow = s_lrow[rloc];
                float s = 0.f;
#pragma unroll
                for (int ni = 0; ni < 4; ni++) {
                    int cl = colloc0 + ni * 8;
                    float s0 = aq[mi][ni][h * 2 + 0] * ak[mi][ni][h * 2 + 0];
                    float s1 = aq[mi][ni][h * 2 + 1] * ak[mi][ni][h * 2 + 1];
                    if (s_lcol[cl] != lrow)     s += nm_term(s0, s_capm[cl], s_sapm[cl]);
                    if (s_lcol[cl + 1] != lrow) s += nm_term(s1, s_capm[cl + 1], s_sapm[cl + 1]);
                }
                s += __shfl_xor_sync(0xffffffffu, s, 1);
                s += __shfl_xor_sync(0xffffffffu, s, 2);
                if ((lane & 3) == 0)
                    atomicAdd(&g_nmp[row], s);
            }
        }
    }
}

// ---------- final combine: 8 blocks, row math parallel, last-block finish ----------
__global__ void __launch_bounds__(256)
final_combine(float* __restrict__ out) {
    int j = blockIdx.x * 256 + threadIdx.x;
    float se = g_rexp[j];
    float sc = g_rsum[j];
    float cyv = g_cy[j];
    float sine = sqrt_approx(fminf(fmaxf(1.f - cyv * cyv, 0.f), 1.f));
    float phi = cyv * K_COSM - sine * K_SINM;
    phi = (cyv - K_TH > 0.f) ? phi : (cyv - K_MM);
    float oy = K_S * phi, ocy = K_S * cyv;
    float sout = K_S * sc + (oy - ocy);
    se += exp_approx(oy - K_S) - exp_approx(ocy - K_S);
    float lse = K_S + log_approx(se);
    float sa = (1.f - K_EPS) * (oy - lse) + (K_EPS / C_) * sout - K_EPS * lse;
    float sn = g_expneg[j];
    float sm = g_nmp[j];
    sa = block_sum_all(sa);
    sn = block_sum_all(sn);
    sm = block_sum_all(sm);
    if (threadIdx.x == 0) {
        atomicAdd(&g_acc[0], sa);
        atomicAdd(&g_acc[1], sn);
        atomicAdd(&g_acc[2], sm);
        __threadfence();
        unsigned t = atomicAdd(&g_ticket, 1u);
        if (t == NFINAL - 1) {
            float fsa = g_acc[0], fsn = g_acc[1], fsm = g_acc[2];
            float aam_loss = -fsa / (float)B_;
            float z = logf(fsm) + logf(fsn);
            float cc = fmaxf(z, 0.f) + log1pf(expf(-fabsf(z)));
            out[0] = aam_loss + cc;
        }
    }
}

// ---------- launcher: 3 launches ----------
extern "C" void kernel_launch(void* const* d_in, const int* in_sizes, int n_in,
                              void* d_out, int out_size) {
    const float* x        = (const float*)d_in[0];
    const int*   label    = (const int*)d_in[1];
    const float* weight   = (const float*)d_in[2];
    const float* weight_m = (const float*)d_in[3];
    const float* weight_n = (const float*)d_in[4];
    float* out = (float*)d_out;

    __nv_bfloat16 *p_xh, *p_wh, *p_wmh, *p_wkh;
    cudaGetSymbolAddress((void**)&p_xh,  g_xh);
    cudaGetSymbolAddress((void**)&p_wh,  g_wh);
    cudaGetSymbolAddress((void**)&p_wmh, g_wmh);
    cudaGetSymbolAddress((void**)&p_wkh, g_wkh);

    cudaFuncSetAttribute(mega_gemm, cudaFuncAttributeMaxDynamicSharedMemorySize, GEMM_SMEM);

    prep_kernel<<<PREP_GRID, 256>>>(x, weight, weight_m, weight_n, label);
    mega_gemm<<<NMEGA, 256, GEMM_SMEM>>>(p_xh, p_wh, p_wmh, p_wkh, label);
    final_combine<<<NFINAL, 256>>>(out);
}